// round 7
// baseline (speedup 1.0000x reference)
#include <cuda_runtime.h>
#include <cuda_bf16.h>
#include <cstdint>
#include <math.h>

// Causal GQA attention. B=1,S=4096,H=8,KVH=2,D=64, fp32 io.
// tcgen05 tf32, RTN operands, software-pipelined, 512 threads.
// MMA1(i+1) issued BEFORE softmax(i) (runs under it); denominator via ones-row.

#define NTHREADS 512

#if defined(__CUDA_ARCH__) && (defined(__CUDA_ARCH_FEAT_SM103_ALL) || \
    defined(__CUDA_ARCH_FEAT_SM100_ALL) || defined(__CUDA_ARCH_SPECIFIC__) || \
    defined(__CUDA_ARCH_FAMILY_SPECIFIC__))
#define TC_PATH 1
#else
#define TC_PATH 0
#endif

#define IDESC_QK ((1u<<4)|(2u<<7)|(2u<<10)|(16u<<17)|(8u<<24))
#define IDESC_PV ((1u<<4)|(2u<<7)|(2u<<10)|( 9u<<17)|(8u<<24))   // N=72 (ones row @64)

static constexpr uint64_t DESC_BASE =       // SW128 K-major, Blackwell
    (uint64_t(2) << 61) | (uint64_t(1) << 46) | (uint64_t(64) << 32) | (uint64_t(1) << 16);

#define Q_OFF     0u
#define K_OFF     32768u          // x2 (32KB each)
#define V_OFF     98304u          // x3 (V^T 72 rows x 512B = 36KB each)
#define VT_STRIDE 36864u
#define CTRL_OFF  208896u         // mbs[2]@+0/+8, mbv[3]@+16/24/32, tmem ptr @+48
#define SMEM_REQ  (208896u + 64u + 1024u)

__device__ __forceinline__ uint32_t smem_u32(const void* p) {
    uint32_t a;
    asm("{ .reg .u64 t; cvta.to.shared.u64 t, %1; cvt.u32.u64 %0, t; }" : "=r"(a) : "l"(p));
    return a;
}
__device__ __forceinline__ uint64_t make_desc(uint32_t a) {
    return DESC_BASE | ((uint64_t)(a >> 4) & 0x3FFF);
}
__device__ __forceinline__ float rnd_tf32(float x) {
    return __uint_as_float((__float_as_uint(x) + 0x1000u) & 0xFFFFE000u);
}

#if TC_PATH
#define FENCE_BEFORE() asm volatile("tcgen05.fence::before_thread_sync;" ::: "memory")
#define FENCE_AFTER()  asm volatile("tcgen05.fence::after_thread_sync;" ::: "memory")
#define FENCE_PROXY()  asm volatile("fence.proxy.async.shared::cta;" ::: "memory")
#define WAIT_LD()      asm volatile("tcgen05.wait::ld.sync.aligned;" ::: "memory")
#define WAIT_ST()      asm volatile("tcgen05.wait::st.sync.aligned;" ::: "memory")
#define MBAR_INIT(m,n) asm volatile("mbarrier.init.shared.b64 [%0], %1;" :: "r"(m), "r"(n) : "memory")
#define MBAR_INVAL(m)  asm volatile("mbarrier.inval.shared.b64 [%0];" :: "r"(m) : "memory")
#define COMMIT(m)      asm volatile("tcgen05.commit.cta_group::1.mbarrier::arrive::one.shared::cluster.b64 [%0];" :: "r"(m) : "memory")

#define MBAR_WAIT(mb, pp) do {                                                    \
    uint32_t _m = (mb), _p = (pp), _d;                                            \
    asm volatile("{\n\t.reg .pred p;\n\t"                                         \
        "mbarrier.try_wait.parity.acquire.cta.shared::cta.b64 p, [%1], %2;\n\t"   \
        "selp.b32 %0, 1, 0, p;\n\t}" : "=r"(_d) : "r"(_m), "r"(_p) : "memory");   \
    if (!_d) {                                                                    \
        asm volatile("{\n\t.reg .pred P1;\n\t"                                    \
            "W_%=:\n\t"                                                           \
            "mbarrier.try_wait.parity.acquire.cta.shared::cta.b64 P1, [%0], %1, 0x989680;\n\t" \
            "@P1 bra.uni D_%=;\n\tbra.uni W_%=;\n\tD_%=:\n\t}"                    \
            :: "r"(_m), "r"(_p) : "memory");                                      \
    }                                                                             \
} while (0)

#define LDTM_X16(r, a)                                                            \
    asm volatile("tcgen05.ld.sync.aligned.32x32b.x16.b32 "                        \
        "{%0,%1,%2,%3,%4,%5,%6,%7,%8,%9,%10,%11,%12,%13,%14,%15}, [%16];"         \
        : "=r"((r)[0]),"=r"((r)[1]),"=r"((r)[2]),"=r"((r)[3]),                    \
          "=r"((r)[4]),"=r"((r)[5]),"=r"((r)[6]),"=r"((r)[7]),                    \
          "=r"((r)[8]),"=r"((r)[9]),"=r"((r)[10]),"=r"((r)[11]),                  \
          "=r"((r)[12]),"=r"((r)[13]),"=r"((r)[14]),"=r"((r)[15]) : "r"(a))

#define STTM_X16(a, r)                                                            \
    asm volatile("tcgen05.st.sync.aligned.32x32b.x16.b32 [%0], "                  \
        "{%1,%2,%3,%4,%5,%6,%7,%8,%9,%10,%11,%12,%13,%14,%15,%16};"               \
        :: "r"(a),                                                                \
          "r"((r)[0]),"r"((r)[1]),"r"((r)[2]),"r"((r)[3]),                        \
          "r"((r)[4]),"r"((r)[5]),"r"((r)[6]),"r"((r)[7]),                        \
          "r"((r)[8]),"r"((r)[9]),"r"((r)[10]),"r"((r)[11]),                      \
          "r"((r)[12]),"r"((r)[13]),"r"((r)[14]),"r"((r)[15]) : "memory")

#define LDTM_X32(r, a)                                                            \
    asm volatile("tcgen05.ld.sync.aligned.32x32b.x32.b32 "                        \
        "{%0,%1,%2,%3,%4,%5,%6,%7,%8,%9,%10,%11,%12,%13,%14,%15,"                 \
        "%16,%17,%18,%19,%20,%21,%22,%23,%24,%25,%26,%27,%28,%29,%30,%31}, [%32];"\
        : "=r"((r)[0]),"=r"((r)[1]),"=r"((r)[2]),"=r"((r)[3]),                    \
          "=r"((r)[4]),"=r"((r)[5]),"=r"((r)[6]),"=r"((r)[7]),                    \
          "=r"((r)[8]),"=r"((r)[9]),"=r"((r)[10]),"=r"((r)[11]),                  \
          "=r"((r)[12]),"=r"((r)[13]),"=r"((r)[14]),"=r"((r)[15]),                \
          "=r"((r)[16]),"=r"((r)[17]),"=r"((r)[18]),"=r"((r)[19]),                \
          "=r"((r)[20]),"=r"((r)[21]),"=r"((r)[22]),"=r"((r)[23]),                \
          "=r"((r)[24]),"=r"((r)[25]),"=r"((r)[26]),"=r"((r)[27]),                \
          "=r"((r)[28]),"=r"((r)[29]),"=r"((r)[30]),"=r"((r)[31]) : "r"(a))

__device__ __forceinline__ void mma_ss(uint32_t d, uint64_t a, uint64_t b,
                                       uint32_t idesc, uint32_t acc) {
    asm volatile("{\n\t.reg .pred p;\n\tsetp.ne.u32 p, %4, 0;\n\t"
        "tcgen05.mma.cta_group::1.kind::tf32 [%0], %1, %2, %3, {%5,%5,%5,%5}, p;\n\t}"
        :: "r"(d), "l"(a), "l"(b), "r"(idesc), "r"(acc), "r"(0u) : "memory");
}
__device__ __forceinline__ void mma_ts(uint32_t d, uint32_t a, uint64_t b,
                                       uint32_t idesc, uint32_t acc) {
    asm volatile("{\n\t.reg .pred p;\n\tsetp.ne.u32 p, %4, 0;\n\t"
        "tcgen05.mma.cta_group::1.kind::tf32 [%0], [%1], %2, %3, {%5,%5,%5,%5}, p;\n\t}"
        :: "r"(d), "r"(a), "l"(b), "r"(idesc), "r"(acc), "r"(0u) : "memory");
}
#endif // TC_PATH

// [128 rows, 64 f32] K-major SW128, atom-blocked; RTN tf32
__device__ __forceinline__ void load_kq(char* dst, const float* src, int row0,
                                        int hstride, int hoff, int tid, float scale) {
    #pragma unroll
    for (int it = 0; it < 2048 / NTHREADS; it++) {
        int idx = it * NTHREADS + tid;
        int row = idx >> 4, c4 = idx & 15;
        float4 v = *(const float4*)(src + ((size_t)(row0 + row) * hstride + hoff) * 64 + (c4 << 2));
        v.x = rnd_tf32(v.x * scale); v.y = rnd_tf32(v.y * scale);
        v.z = rnd_tf32(v.z * scale); v.w = rnd_tf32(v.w * scale);
        uint32_t b = (uint32_t)((((row >> 3) + ((c4 >> 3) << 4)) << 10)
                   | ((row & 7) << 7) | ((c4 & 7) << 4));
        b ^= (b >> 3) & 0x70;
        *(float4*)(dst + b) = v;
    }
}
// V^T: [72 rows, 128 cols=k]; atom = (d>>3) + (kb>>3)*9
__device__ __forceinline__ void load_vt(char* dst, const float* V,
                                        int k0, int kvh, int tid) {
    int kb = tid & 31, db = tid >> 5;
    const float* vb = V + ((size_t)(k0 + (kb << 2)) * 2 + kvh) * 64 + (db << 2);
    const size_t rs = 2 * 64;
    float4 r0 = *(const float4*)(vb);
    float4 r1 = *(const float4*)(vb + rs);
    float4 r2 = *(const float4*)(vb + 2 * rs);
    float4 r3 = *(const float4*)(vb + 3 * rs);
    const float* a0 = (const float*)&r0; const float* a1 = (const float*)&r1;
    const float* a2 = (const float*)&r2; const float* a3 = (const float*)&r3;
    #pragma unroll
    for (int j = 0; j < 4; j++) {
        int d = (db << 2) + j;
        float4 w;
        w.x = rnd_tf32(a0[j]); w.y = rnd_tf32(a1[j]);
        w.z = rnd_tf32(a2[j]); w.w = rnd_tf32(a3[j]);
        uint32_t b = (uint32_t)((((d >> 3) + (kb >> 3) * 9) << 10)
                   | ((d & 7) << 7) | ((kb & 7) << 4));
        b ^= (b >> 3) & 0x70;
        *(float4*)(dst + b) = w;
    }
}

__global__ void __launch_bounds__(NTHREADS, 1)
attn_kernel(const float* __restrict__ Q, const float* __restrict__ K,
            const float* __restrict__ V, float* __restrict__ Out, int S)
{
    extern __shared__ char smem_raw[];

#if TC_PATH
    uint32_t s_raw = smem_u32(smem_raw);
    uint32_t pad = (1024u - (s_raw & 1023u)) & 1023u;
    char* sm = smem_raw + pad;
    const uint32_t sb = s_raw + pad;

    const uint32_t mbs  = sb + CTRL_OFF;               // mbs[2]: MMA1 ping-pong
    const uint32_t mbv  = sb + CTRL_OFF + 16;          // mbv[3]: MMA2 V-slots
    const uint32_t tptr = sb + CTRL_OFF + 48;

    const int tid = threadIdx.x, w = tid >> 5, lane = tid & 31;
    const int nq = S >> 7;
    const int h  = blockIdx.x & 7;
    const int qt = nq - 1 - (blockIdx.x >> 3);          // largest tiles first
    const int kvh = h >> 2;
    const int q0 = qt << 7;
    const int T  = qt + 1;

    if (w == 0) {
        asm volatile("tcgen05.alloc.cta_group::1.sync.aligned.shared::cta.b32 [%0], 512;"
                     :: "r"(tptr) : "memory");
        asm volatile("tcgen05.relinquish_alloc_permit.cta_group::1.sync.aligned;");
    }
    if (tid == 0) {
        MBAR_INIT(mbs, 1); MBAR_INIT(mbs + 8, 1);
        MBAR_INIT(mbv, 1); MBAR_INIT(mbv + 8, 1); MBAR_INIT(mbv + 16, 1);
    }
    // Q resident: pre-scaled by 1/8 * log2(e)
    load_kq(sm + Q_OFF, Q, q0, 8, h, tid, 0.125f * 1.4426950408889634f);
    load_kq(sm + K_OFF, K, 0, 2, kvh, tid, 1.0f);
    load_vt(sm + V_OFF, V, 0, kvh, tid);
    // static rows 64..71 of all 3 V^T buffers: row 64 = 1.0, rest 0
    for (int t = tid; t < 768; t += NTHREADS) {
        int buf = t >> 8, s2 = t & 255;
        int d = 64 + (s2 >> 5), kb = s2 & 31;
        float val = (d == 64) ? 1.0f : 0.0f;
        uint32_t b = (uint32_t)((((d >> 3) + (kb >> 3) * 9) << 10)
                   | ((d & 7) << 7) | ((kb & 7) << 4));
        b ^= (b >> 3) & 0x70;
        *(float4*)(sm + V_OFF + (uint32_t)buf * VT_STRIDE + b) = make_float4(val, val, val, val);
    }
    FENCE_PROXY();
    __syncthreads();
    uint32_t tb;
    asm volatile("ld.shared.b32 %0, [%1];" : "=r"(tb) : "r"(tptr));
    const uint32_t oreg = tb;                 // O: 72 cols
    const uint32_t sregs[2] = { tb + 128, tb + 256 };

    const uint64_t dQ = make_desc(sb + Q_OFF);

    if (tid == 0) {       // MMA1(0) -> mbs[0]
        FENCE_AFTER();
        uint64_t dk = make_desc(sb + K_OFF);
        #pragma unroll
        for (int k = 0; k < 8; k++) {
            uint64_t o = (uint64_t)(((k >> 2) << 10) | ((k & 3) << 1));
            mma_ss(sregs[0], dQ + o, dk + o, IDESC_QK, k > 0);
        }
        COMMIT(mbs);
    }

    const int sub = w & 3;
    const int cb  = (w >> 2) * 32;            // column block base
    const uint32_t woff = (uint32_t)sub << 21;
    const int row = (sub << 5) + lane;

    for (int i = 0; i < T; i++) {
        // A) prefetch tiles for step i+1
        if (i + 1 < T) {
            if (i + 1 >= 3)
                MBAR_WAIT(mbv + 8u * (uint32_t)((i + 1) % 3), (uint32_t)(((i - 2) / 3) & 1));
            load_kq(sm + K_OFF + (uint32_t)((i + 1) & 1) * 32768u, K, (i + 1) << 7, 2, kvh, tid, 1.0f);
            load_vt(sm + V_OFF + (uint32_t)((i + 1) % 3) * VT_STRIDE, V, (i + 1) << 7, kvh, tid);
            FENCE_PROXY();
        }
        __syncthreads();                       // loads visible to tid0

        // B) EARLY MMA1(i+1): runs on tensor pipe while we softmax(i).
        //    In-order pipe orders its S-region write after MMA2(i-1)'s read.
        if (tid == 0 && i + 1 < T) {
            FENCE_AFTER();
            uint64_t dk = make_desc(sb + K_OFF + (uint32_t)((i + 1) & 1) * 32768u);
            #pragma unroll
            for (int k = 0; k < 8; k++) {
                uint64_t o = (uint64_t)(((k >> 2) << 10) | ((k & 3) << 1));
                mma_ss(sregs[(i + 1) & 1], dQ + o, dk + o, IDESC_QK, k > 0);
            }
            COMMIT(mbs + 8u * (uint32_t)((i + 1) & 1));
        }

        // C) wait MMA1(i), softmax in place (split halves to overlap LDTM+MUFU)
        MBAR_WAIT(mbs + 8u * (uint32_t)(i & 1), (uint32_t)((i >> 1) & 1));
        FENCE_AFTER();
        const uint32_t scur = sregs[i & 1];
        uint32_t r0[16], r1[16];
        LDTM_X16(r0, scur + (uint32_t)cb + woff);
        WAIT_LD();
        LDTM_X16(r1, scur + (uint32_t)cb + 16u + woff);
        if (i == T - 1) {
            const int lim = row - cb;
            #pragma unroll
            for (int j = 0; j < 16; j++) {
                float p;
                asm("ex2.approx.ftz.f32 %0, %1;" : "=f"(p) : "f"(__uint_as_float(r0[j])));
                r0[j] = __float_as_uint((j <= lim) ? rnd_tf32(p) : 0.0f);
            }
            WAIT_LD();
            #pragma unroll
            for (int j = 0; j < 16; j++) {
                float p;
                asm("ex2.approx.ftz.f32 %0, %1;" : "=f"(p) : "f"(__uint_as_float(r1[j])));
                r1[j] = __float_as_uint((j + 16 <= lim) ? rnd_tf32(p) : 0.0f);
            }
        } else {
            #pragma unroll
            for (int j = 0; j < 16; j++) {
                float p;
                asm("ex2.approx.ftz.f32 %0, %1;" : "=f"(p) : "f"(__uint_as_float(r0[j])));
                r0[j] = __float_as_uint(rnd_tf32(p));
            }
            WAIT_LD();
            #pragma unroll
            for (int j = 0; j < 16; j++) {
                float p;
                asm("ex2.approx.ftz.f32 %0, %1;" : "=f"(p) : "f"(__uint_as_float(r1[j])));
                r1[j] = __float_as_uint(rnd_tf32(p));
            }
        }
        STTM_X16(scur + (uint32_t)cb + woff, r0);
        STTM_X16(scur + (uint32_t)cb + 16u + woff, r1);
        WAIT_ST();
        FENCE_BEFORE();
        __syncthreads();

        // D) MMA2(i): O += P * V^T  (N=72, col 64 = sum_k P)
        if (tid == 0) {
            FENCE_AFTER();
            uint64_t dv = make_desc(sb + V_OFF + (uint32_t)(i % 3) * VT_STRIDE);
            #pragma unroll
            for (int j = 0; j < 16; j++) {
                uint64_t o = (uint64_t)((j >> 2) * 576 + ((j & 3) << 1));
                mma_ts(oreg, scur + (uint32_t)(j * 8), dv + o, IDESC_PV, (i > 0) || (j > 0));
            }
            COMMIT(mbv + 8u * (uint32_t)(i % 3));
        }
    }

    MBAR_WAIT(mbv + 8u * (uint32_t)((T - 1) % 3), (uint32_t)(((T - 1) / 3) & 1));
    FENCE_AFTER();

    if (w < 8) {                               // epilogue: 8 warps
        const int half = w >> 2;
        uint32_t r[32], rl;
        LDTM_X32(r, oreg + (uint32_t)(half * 32) + woff);
        asm volatile("tcgen05.ld.sync.aligned.32x32b.x1.b32 {%0}, [%1];"
                     : "=r"(rl) : "r"(oreg + 64u + woff));
        WAIT_LD();
        const float inv = 1.0f / __uint_as_float(rl);
        float* op = Out + ((size_t)(q0 + row) * 8 + h) * 64 + half * 32;
        #pragma unroll
        for (int j = 0; j < 8; j++) {
            float4 t;
            t.x = __uint_as_float(r[j * 4 + 0]) * inv;
            t.y = __uint_as_float(r[j * 4 + 1]) * inv;
            t.z = __uint_as_float(r[j * 4 + 2]) * inv;
            t.w = __uint_as_float(r[j * 4 + 3]) * inv;
            *(float4*)(op + j * 4) = t;
        }
    }
    __syncthreads();
    if (tid == 0) {
        MBAR_INVAL(mbs); MBAR_INVAL(mbs + 8);
        MBAR_INVAL(mbv); MBAR_INVAL(mbv + 8); MBAR_INVAL(mbv + 16);
    }
    if (w == 0)
        asm volatile("tcgen05.dealloc.cta_group::1.sync.aligned.b32 %0, 512;" :: "r"(tb));

#else
    // ───────────────── SIMT fallback (no tcgen05 in this target) ─────────
    float* skf = (float*)smem_raw;            // [64][64]
    float* svf = skf + 4096;

    const int tid  = threadIdx.x;
    const int nq   = S >> 7;
    const int h    = blockIdx.x & 7;
    const int qt   = nq - 1 - (blockIdx.x >> 3);
    const int kvh  = h >> 2;
    const int q0   = qt << 7;
    const int row  = tid >> 2;
    const int dq   = tid & 3;
    const int qidx = q0 + row;

    float qreg[16], acc[16];
    {
        const float4* qp = (const float4*)(Q + ((size_t)qidx * 8 + h) * 64 + dq * 16);
        #pragma unroll
        for (int i = 0; i < 4; i++) {
            float4 t = qp[i];
            qreg[i*4+0] = t.x * 0.125f; qreg[i*4+1] = t.y * 0.125f;
            qreg[i*4+2] = t.z * 0.125f; qreg[i*4+3] = t.w * 0.125f;
        }
    }
    #pragma unroll
    for (int d = 0; d < 16; d++) acc[d] = 0.f;
    float l = 0.f;

    for (int k0 = 0; k0 <= q0 + 127; k0 += 64) {
        __syncthreads();
        #pragma unroll
        for (int i = 0; i < 2; i++) {
            int idx = i * NTHREADS + tid;
            int r = idx >> 4, c = idx & 15;
            size_t g = ((size_t)(k0 + r) * 2 + kvh) * 64;
            *(float4*)(skf + r * 64 + c * 4) = *(const float4*)(K + g + c * 4);
            *(float4*)(svf + r * 64 + c * 4) = *(const float4*)(V + g + c * 4);
        }
        __syncthreads();

        int jmax = qidx - k0 + 1;
        if (jmax > 64) jmax = 64;
        for (int j = 0; j < jmax; j++) {
            const float* kj = skf + j * 64 + dq * 16;
            float s0 = 0.f, s1 = 0.f, s2 = 0.f, s3 = 0.f;
            #pragma unroll
            for (int d = 0; d < 16; d += 4) {
                s0 += qreg[d+0] * kj[d+0];
                s1 += qreg[d+1] * kj[d+1];
                s2 += qreg[d+2] * kj[d+2];
                s3 += qreg[d+3] * kj[d+3];
            }
            float sp = (s0 + s1) + (s2 + s3);
            sp += __shfl_xor_sync(0xFFFFFFFFu, sp, 1);
            sp += __shfl_xor_sync(0xFFFFFFFFu, sp, 2);
            float p = __expf(fminf(sp, 30.f));
            l += p;
            const float* vj = svf + j * 64 + dq * 16;
            #pragma unroll
            for (int d = 0; d < 16; d++) acc[d] += p * vj[d];
        }
    }

    float inv = 1.0f / l;
    float4* op = (float4*)(Out + ((size_t)qidx * 8 + h) * 64 + dq * 16);
    #pragma unroll
    for (int i = 0; i < 4; i++) {
        float4 t;
        t.x = acc[i*4+0] * inv; t.y = acc[i*4+1] * inv;
        t.z = acc[i*4+2] * inv; t.w = acc[i*4+3] * inv;
        op[i] = t;
    }
#endif
}

extern "C" void kernel_launch(void* const* d_in, const int* in_sizes, int n_in,
                              void* d_out, int out_size)
{
    const float* Q = (const float*)d_in[0];
    const float* K = (const float*)d_in[1];
    const float* V = (const float*)d_in[2];
    float* Out = (float*)d_out;
    const int S = in_sizes[0] / (8 * 64);   // 4096

    cudaFuncSetAttribute(attn_kernel,
                         cudaFuncAttributeMaxDynamicSharedMemorySize, SMEM_REQ);
    dim3 grid((S >> 7) * 8);
    attn_kernel<<<grid, NTHREADS, SMEM_REQ>>>(Q, K, V, Out, S);
}